// round 2
// baseline (speedup 1.0000x reference)
#include <cuda_runtime.h>

#define NTHREADS 256
#define PRIME_X 73856093u
#define PRIME_Y 19349663u
#define PRIME_Z 83492791u

constexpr int OFF_T0 = 0;
constexpr int OFF_T1 = OFF_T0 + 50 * 33;
constexpr int OFF_T2 = OFF_T1 + 200 * 17;
constexpr int OFF_T3 = OFF_T2 + 400 * 9;
constexpr int OFF_T4 = OFF_T3 + 400 * 5;
constexpr int OFF_TEND = OFF_T4 + 400 * 3;
constexpr int OFF_W1D = ((OFF_TEND + 3) / 4) * 4;   // 16B-aligned
constexpr int OFF_W1C = OFF_W1D + 63 * 64;
constexpr int OFF_B1D = OFF_W1C + 63 * 64;
constexpr int OFF_B1C = OFF_B1D + 64;
constexpr int OFF_W2D = OFF_B1C + 64;
constexpr int OFF_W2C = OFF_W2D + 64;
constexpr int SMEM_FLOATS = OFF_W2C + 3 * 64;
constexpr int SMEM_BYTES = SMEM_FLOATS * 4;

__device__ __forceinline__ unsigned long long pk2(float a, float b) {
    unsigned long long r;
    asm("mov.b64 %0, {%1, %2};" : "=l"(r) : "f"(a), "f"(b));
    return r;
}
__device__ __forceinline__ void fma2(unsigned long long& d, unsigned long long a,
                                     unsigned long long b) {
    asm("fma.rn.f32x2 %0, %1, %2, %0;" : "+l"(d) : "l"(a), "l"(b));
}
__device__ __forceinline__ void upk2(unsigned long long v, float& a, float& b) {
    asm("mov.b64 {%0, %1}, %2;" : "=f"(a), "=f"(b) : "l"(v));
}

template <int H, int D, int S, int BASE>
__device__ __forceinline__ void encode_level(const float* __restrict__ sT,
                                             float px, float py, float pz,
                                             float (&feat)[63]) {
    float fx = floorf(px), fy = floorf(py), fz = floorf(pz);
    float rx = px - fx, ry = py - fy, rz = pz - fz;
    int fxi = (int)fx, fyi = (int)fy, fzi = (int)fz;
    int cxi = (int)ceilf(px), cyi = (int)ceilf(py), czi = (int)ceilf(pz);

    int hx0 = (int)((unsigned)fxi * PRIME_X);
    int hx1 = (int)((unsigned)cxi * PRIME_X);
    int hy0 = (int)((unsigned)fyi * PRIME_Y);
    int hy1 = (int)((unsigned)cyi * PRIME_Y);
    int hz0 = (int)((unsigned)fzi * PRIME_Z);
    int hz1 = (int)((unsigned)czi * PRIME_Z);

    // reference quirk: FLOOR corner weighted by r, CEIL corner by (1-r)
    float wx0 = rx, wx1 = 1.0f - rx;
    float wy0 = ry, wy1 = 1.0f - ry;
    float wz0 = rz, wz1 = 1.0f - rz;

#pragma unroll
    for (int c = 0; c < 8; c++) {
        const int bi = (c >> 2) & 1, bj = (c >> 1) & 1, bk = c & 1;
        int v = (bi ? hx1 : hx0) ^ (bj ? hy1 : hy0) ^ (bk ? hz1 : hz0);
        int h = v % H;
        if (h < 0) h += H;  // Python-style nonneg mod
        float w = (bi ? wx1 : wx0) * (bj ? wy1 : wy0) * (bk ? wz1 : wz0);
        const float* row = sT + h * S;
#pragma unroll
        for (int d = 0; d < D; d++) feat[BASE + d] = fmaf(w, row[d], feat[BASE + d]);
    }
}

template <int NO>
__device__ __forceinline__ void mlp_pass(const float* __restrict__ sW1,
                                         const float* __restrict__ sb1,
                                         const float* __restrict__ sW2,
                                         const float (&feat)[63], float (&out)[NO]) {
#pragma unroll
    for (int t = 0; t < 4; t++) {  // 4 tiles of 16 hidden units
        unsigned long long acc[8];
#pragma unroll
        for (int c = 0; c < 8; c++) {
            const float2 b = *(const float2*)&sb1[t * 16 + 2 * c];
            acc[c] = pk2(b.x, b.y);
        }
#pragma unroll
        for (int j = 0; j < 63; j++) {
            const unsigned long long fj2 = pk2(feat[j], feat[j]);
            const ulonglong2* wp = (const ulonglong2*)&sW1[j * 64 + t * 16];
#pragma unroll
            for (int q = 0; q < 4; q++) {       // 4 x 16B = full 16-float tile
                const ulonglong2 wv = wp[q];
                fma2(acc[2 * q + 0], fj2, wv.x);
                fma2(acc[2 * q + 1], fj2, wv.y);
            }
        }
#pragma unroll
        for (int c = 0; c < 8; c++) {
            float h0, h1;
            upk2(acc[c], h0, h1);
            h0 = fmaxf(h0, 0.0f);
            h1 = fmaxf(h1, 0.0f);
#pragma unroll
            for (int o = 0; o < NO; o++) {
                out[o] = fmaf(h0, sW2[o * 64 + t * 16 + 2 * c], out[o]);
                out[o] = fmaf(h1, sW2[o * 64 + t * 16 + 2 * c + 1], out[o]);
            }
        }
    }
}

template <int H, int D, int S>
__device__ __forceinline__ void load_table(float* dst, const float* __restrict__ src,
                                           int tid) {
    for (int i = tid; i < H * D; i += NTHREADS) {
        int r = i / D, c = i - r * D;
        dst[r * S + c] = src[i];
    }
}

__global__ void __launch_bounds__(NTHREADS)
nerf_fused_kernel(const float* __restrict__ x, const float* __restrict__ e0,
                  const float* __restrict__ e1, const float* __restrict__ e2,
                  const float* __restrict__ e3, const float* __restrict__ e4,
                  const float* __restrict__ Wd1, const float* __restrict__ bd1,
                  const float* __restrict__ Wd2, const float* __restrict__ bd2,
                  const float* __restrict__ Wc1, const float* __restrict__ bc1,
                  const float* __restrict__ Wc2, const float* __restrict__ bc2,
                  float* __restrict__ out, int N) {
    extern __shared__ float sm[];
    const int tid = threadIdx.x;

    load_table<50, 32, 33>(sm + OFF_T0, e0, tid);
    load_table<200, 16, 17>(sm + OFF_T1, e1, tid);
    load_table<400, 8, 9>(sm + OFF_T2, e2, tid);
    load_table<400, 4, 5>(sm + OFF_T3, e3, tid);
    load_table<400, 3, 3>(sm + OFF_T4, e4, tid);
    for (int i = tid; i < 63 * 64; i += NTHREADS) {
        int j = i >> 6, o = i & 63;
        sm[OFF_W1D + i] = (o < 63) ? Wd1[j * 63 + o] : 0.0f;
        sm[OFF_W1C + i] = (o < 63) ? Wc1[j * 63 + o] : 0.0f;
    }
    for (int i = tid; i < 64; i += NTHREADS) {
        sm[OFF_B1D + i] = (i < 63) ? bd1[i] : 0.0f;
        sm[OFF_B1C + i] = (i < 63) ? bc1[i] : 0.0f;
        sm[OFF_W2D + i] = (i < 63) ? Wd2[i] : 0.0f;
    }
    for (int i = tid; i < 3 * 64; i += NTHREADS) {
        int ch = i >> 6, o = i & 63;
        sm[OFF_W2C + i] = (o < 63) ? Wc2[o * 3 + ch] : 0.0f;
    }
    __syncthreads();

    const int idx = blockIdx.x * NTHREADS + tid;
    if (idx >= N) return;

    const float xv = x[idx * 3 + 0];
    const float yv = x[idx * 3 + 1];
    const float zv = x[idx * 3 + 2];

    float feat[63];
#pragma unroll
    for (int i = 0; i < 63; i++) feat[i] = 0.0f;

    // vsl = 1.0, 0.5, 0.25, 0.125 are exact power-of-two scalings; 0.05 via div.
    encode_level<50, 32, 33, 0>(sm + OFF_T0, xv, yv, zv, feat);
    encode_level<200, 16, 17, 32>(sm + OFF_T1, xv * 2.0f, yv * 2.0f, zv * 2.0f, feat);
    encode_level<400, 8, 9, 48>(sm + OFF_T2, xv * 4.0f, yv * 4.0f, zv * 4.0f, feat);
    encode_level<400, 4, 5, 56>(sm + OFF_T3, xv * 8.0f, yv * 8.0f, zv * 8.0f, feat);
    encode_level<400, 3, 3, 60>(sm + OFF_T4, __fdiv_rn(xv, 0.05f),
                                __fdiv_rn(yv, 0.05f), __fdiv_rn(zv, 0.05f), feat);

    float dacc[1] = {bd2[0]};
    mlp_pass<1>(sm + OFF_W1D, sm + OFF_B1D, sm + OFF_W2D, feat, dacc);
    float cacc[3] = {bc2[0], bc2[1], bc2[2]};
    mlp_pass<3>(sm + OFF_W1C, sm + OFF_B1C, sm + OFF_W2C, feat, cacc);

    out[idx] = dacc[0];                 // dense (N,1) flat
    out[N + idx * 3 + 0] = cacc[0];     // color (N,3) row-major after dense
    out[N + idx * 3 + 1] = cacc[1];
    out[N + idx * 3 + 2] = cacc[2];
}

extern "C" void kernel_launch(void* const* d_in, const int* in_sizes, int n_in,
                              void* d_out, int out_size) {
    const float* x = (const float*)d_in[0];
    const float* e0 = (const float*)d_in[1];
    const float* e1 = (const float*)d_in[2];
    const float* e2 = (const float*)d_in[3];
    const float* e3 = (const float*)d_in[4];
    const float* e4 = (const float*)d_in[5];
    const float* Wd1 = (const float*)d_in[6];
    const float* bd1 = (const float*)d_in[7];
    const float* Wd2 = (const float*)d_in[8];
    const float* bd2 = (const float*)d_in[9];
    const float* Wc1 = (const float*)d_in[10];
    const float* bc1 = (const float*)d_in[11];
    const float* Wc2 = (const float*)d_in[12];
    const float* bc2 = (const float*)d_in[13];

    const int N = in_sizes[0] / 3;
    float* out = (float*)d_out;

    cudaFuncSetAttribute(nerf_fused_kernel,
                         cudaFuncAttributeMaxDynamicSharedMemorySize, SMEM_BYTES);

    const int grid = (N + NTHREADS - 1) / NTHREADS;
    nerf_fused_kernel<<<grid, NTHREADS, SMEM_BYTES>>>(
        x, e0, e1, e2, e3, e4, Wd1, bd1, Wd2, bd2, Wc1, bc1, Wc2, bc2, out, N);
}

// round 4
// speedup vs baseline: 1.0054x; 1.0054x over previous
#include <cuda_runtime.h>

#define NTHREADS 256
#define PRIME_X 73856093u
#define PRIME_Y 19349663u
#define PRIME_Z 83492791u

// Table strides (floats): 16B-aligned, chunk index spreads over bank groups.
constexpr int OFF_T0 = 0;                    // 50 x 32, stride 36
constexpr int OFF_T1 = OFF_T0 + 50 * 36;     // 200 x 16, stride 20
constexpr int OFF_T2 = OFF_T1 + 200 * 20;    // 400 x 8,  stride 12
constexpr int OFF_T3 = OFF_T2 + 400 * 12;    // 400 x 4,  stride 4
constexpr int OFF_T4 = OFF_T3 + 400 * 4;     // 400 x 3,  stride 4 (pad)
constexpr int OFF_TEND = OFF_T4 + 400 * 4;   // 13800
constexpr int OFF_W1D = OFF_TEND;            // 63 x 64 (col 63 zero)
constexpr int OFF_W1C = OFF_W1D + 63 * 64;
constexpr int OFF_B1D = OFF_W1C + 63 * 64;   // 64
constexpr int OFF_B1C = OFF_B1D + 64;
constexpr int OFF_W2D = OFF_B1C + 64;        // 64
constexpr int OFF_W2C = OFF_W2D + 64;        // 3 x 64 (transposed)
constexpr int SMEM_FLOATS = OFF_W2C + 3 * 64;
constexpr int SMEM_BYTES = SMEM_FLOATS * 4;  // ~89 KB

__device__ __forceinline__ unsigned long long pk2(float a, float b) {
    unsigned long long r;
    asm("mov.b64 %0, {%1, %2};" : "=l"(r) : "f"(a), "f"(b));
    return r;
}
__device__ __forceinline__ void fma2(unsigned long long& d, unsigned long long a,
                                     unsigned long long b) {
    asm("fma.rn.f32x2 %0, %1, %2, %0;" : "+l"(d) : "l"(a), "l"(b));
}
__device__ __forceinline__ void upk2(unsigned long long v, float& a, float& b) {
    asm("mov.b64 {%0, %1}, %2;" : "=f"(a), "=f"(b) : "l"(v));
}

// ---------------- hash-grid encode (vectorized LDS.128 gathers) -------------
template <int H, int D, int S, int BASE>
__device__ __forceinline__ void encode_level(const float* __restrict__ sT,
                                             float px, float py, float pz,
                                             float (&feat)[63]) {
    float fx = floorf(px), fy = floorf(py), fz = floorf(pz);
    float rx = px - fx, ry = py - fy, rz = pz - fz;
    int fxi = (int)fx, fyi = (int)fy, fzi = (int)fz;
    int cxi = (int)ceilf(px), cyi = (int)ceilf(py), czi = (int)ceilf(pz);

    int hx0 = (int)((unsigned)fxi * PRIME_X);
    int hx1 = (int)((unsigned)cxi * PRIME_X);
    int hy0 = (int)((unsigned)fyi * PRIME_Y);
    int hy1 = (int)((unsigned)cyi * PRIME_Y);
    int hz0 = (int)((unsigned)fzi * PRIME_Z);
    int hz1 = (int)((unsigned)czi * PRIME_Z);

    // reference quirk: FLOOR corner weighted by r, CEIL corner by (1-r)
    float wx0 = rx, wx1 = 1.0f - rx;
    float wy0 = ry, wy1 = 1.0f - ry;
    float wz0 = rz, wz1 = 1.0f - rz;

    constexpr int D4 = (D + 3) / 4;
#pragma unroll
    for (int c = 0; c < 8; c++) {
        const int bi = (c >> 2) & 1, bj = (c >> 1) & 1, bk = c & 1;
        int v = (bi ? hx1 : hx0) ^ (bj ? hy1 : hy0) ^ (bk ? hz1 : hz0);
        int h = v % H;
        if (h < 0) h += H;  // Python-style nonneg mod
        float w = (bi ? wx1 : wx0) * (bj ? wy1 : wy0) * (bk ? wz1 : wz0);
        const float4* row = (const float4*)(sT + h * S);
#pragma unroll
        for (int q = 0; q < D4; q++) {
            float4 rv = row[q];
            feat[BASE + 4 * q + 0] = fmaf(w, rv.x, feat[BASE + 4 * q + 0]);
            if (4 * q + 1 < D) feat[BASE + 4 * q + 1] = fmaf(w, rv.y, feat[BASE + 4 * q + 1]);
            if (4 * q + 2 < D) feat[BASE + 4 * q + 2] = fmaf(w, rv.z, feat[BASE + 4 * q + 2]);
            if (4 * q + 3 < D) feat[BASE + 4 * q + 3] = fmaf(w, rv.w, feat[BASE + 4 * q + 3]);
        }
    }
}

// ---------------- fused MLP head: 63 -> 63(relu) -> NO ----------------------
// sW1: 63 rows x 64 cols (col 63 zero). sW2: NO x 64 (transposed, zero-pad).
template <int NO>
__device__ __forceinline__ void mlp_head(const float* __restrict__ sW1,
                                         const float* __restrict__ sb1,
                                         const float* __restrict__ sW2,
                                         const float (&feat)[63], float (&out)[NO]) {
#pragma unroll
    for (int t = 0; t < 2; t++) {  // 2 passes of 32 hidden units
        unsigned long long acc[16];
#pragma unroll
        for (int c = 0; c < 16; c++) {
            const float2 b = *(const float2*)&sb1[t * 32 + 2 * c];
            acc[c] = pk2(b.x, b.y);
        }
#pragma unroll 7
        for (int j = 0; j < 63; j++) {
            const unsigned long long fj2 = pk2(feat[j], feat[j]);
            const ulonglong2* wp = (const ulonglong2*)&sW1[j * 64 + t * 32];
#pragma unroll
            for (int q = 0; q < 8; q++) {  // 8 x 16B = 32 floats
                const ulonglong2 wv = wp[q];
                fma2(acc[2 * q + 0], fj2, wv.x);
                fma2(acc[2 * q + 1], fj2, wv.y);
            }
        }
#pragma unroll
        for (int c = 0; c < 16; c++) {
            float h0, h1;
            upk2(acc[c], h0, h1);
            h0 = fmaxf(h0, 0.0f);
            h1 = fmaxf(h1, 0.0f);
#pragma unroll
            for (int o = 0; o < NO; o++) {
                out[o] = fmaf(h0, sW2[o * 64 + t * 32 + 2 * c], out[o]);
                out[o] = fmaf(h1, sW2[o * 64 + t * 32 + 2 * c + 1], out[o]);
            }
        }
    }
}

template <int H, int D, int S>
__device__ __forceinline__ void load_table(float* dst, const float* __restrict__ src,
                                           int tid) {
    for (int i = tid; i < H * D; i += NTHREADS) {
        int r = i / D, c = i - r * D;
        dst[r * S + c] = src[i];
    }
}

__global__ void __launch_bounds__(NTHREADS, 2)
nerf_fused_kernel(const float* __restrict__ x, const float* __restrict__ e0,
                  const float* __restrict__ e1, const float* __restrict__ e2,
                  const float* __restrict__ e3, const float* __restrict__ e4,
                  const float* __restrict__ Wd1, const float* __restrict__ bd1,
                  const float* __restrict__ Wd2, const float* __restrict__ bd2,
                  const float* __restrict__ Wc1, const float* __restrict__ bc1,
                  const float* __restrict__ Wc2, const float* __restrict__ bc2,
                  float* __restrict__ out, int N) {
    extern __shared__ float sm[];
    const int tid = threadIdx.x;

    load_table<50, 32, 36>(sm + OFF_T0, e0, tid);
    load_table<200, 16, 20>(sm + OFF_T1, e1, tid);
    load_table<400, 8, 12>(sm + OFF_T2, e2, tid);
    load_table<400, 4, 4>(sm + OFF_T3, e3, tid);
    load_table<400, 3, 4>(sm + OFF_T4, e4, tid);
    for (int i = tid; i < 63 * 64; i += NTHREADS) {
        int j = i >> 6, o = i & 63;
        sm[OFF_W1D + i] = (o < 63) ? Wd1[j * 63 + o] : 0.0f;
        sm[OFF_W1C + i] = (o < 63) ? Wc1[j * 63 + o] : 0.0f;
    }
    for (int i = tid; i < 64; i += NTHREADS) {
        sm[OFF_B1D + i] = (i < 63) ? bd1[i] : 0.0f;
        sm[OFF_B1C + i] = (i < 63) ? bc1[i] : 0.0f;
        sm[OFF_W2D + i] = (i < 63) ? Wd2[i] : 0.0f;
    }
    for (int i = tid; i < 3 * 64; i += NTHREADS) {
        int ch = i >> 6, o = i & 63;
        sm[OFF_W2C + i] = (o < 63) ? Wc2[o * 3 + ch] : 0.0f;
    }
    __syncthreads();

    const int idx = blockIdx.x * NTHREADS + tid;
    if (idx >= N) return;

    const float xv = x[idx * 3 + 0];
    const float yv = x[idx * 3 + 1];
    const float zv = x[idx * 3 + 2];

    float feat[63];
#pragma unroll
    for (int i = 0; i < 63; i++) feat[i] = 0.0f;

    // vsl = 1.0, 0.5, 0.25, 0.125 exact pow2 scalings; 0.05 via true division.
    encode_level<50, 32, 36, 0>(sm + OFF_T0, xv, yv, zv, feat);
    encode_level<200, 16, 20, 32>(sm + OFF_T1, xv * 2.0f, yv * 2.0f, zv * 2.0f, feat);
    encode_level<400, 8, 12, 48>(sm + OFF_T2, xv * 4.0f, yv * 4.0f, zv * 4.0f, feat);
    encode_level<400, 4, 4, 56>(sm + OFF_T3, xv * 8.0f, yv * 8.0f, zv * 8.0f, feat);
    encode_level<400, 3, 4, 60>(sm + OFF_T4, __fdiv_rn(xv, 0.05f),
                                __fdiv_rn(yv, 0.05f), __fdiv_rn(zv, 0.05f), feat);

    float dacc[1] = {bd2[0]};
    mlp_head<1>(sm + OFF_W1D, sm + OFF_B1D, sm + OFF_W2D, feat, dacc);
    float cacc[3] = {bc2[0], bc2[1], bc2[2]};
    mlp_head<3>(sm + OFF_W1C, sm + OFF_B1C, sm + OFF_W2C, feat, cacc);

    out[idx] = dacc[0];
    out[N + idx * 3 + 0] = cacc[0];
    out[N + idx * 3 + 1] = cacc[1];
    out[N + idx * 3 + 2] = cacc[2];
}

extern "C" void kernel_launch(void* const* d_in, const int* in_sizes, int n_in,
                              void* d_out, int out_size) {
    const float* x = (const float*)d_in[0];
    const float* e0 = (const float*)d_in[1];
    const float* e1 = (const float*)d_in[2];
    const float* e2 = (const float*)d_in[3];
    const float* e3 = (const float*)d_in[4];
    const float* e4 = (const float*)d_in[5];
    const float* Wd1 = (const float*)d_in[6];
    const float* bd1 = (const float*)d_in[7];
    const float* Wd2 = (const float*)d_in[8];
    const float* bd2 = (const float*)d_in[9];
    const float* Wc1 = (const float*)d_in[10];
    const float* bc1 = (const float*)d_in[11];
    const float* Wc2 = (const float*)d_in[12];
    const float* bc2 = (const float*)d_in[13];

    const int N = in_sizes[0] / 3;
    float* out = (float*)d_out;

    cudaFuncSetAttribute(nerf_fused_kernel,
                         cudaFuncAttributeMaxDynamicSharedMemorySize, SMEM_BYTES);

    const int grid = (N + NTHREADS - 1) / NTHREADS;
    nerf_fused_kernel<<<grid, NTHREADS, SMEM_BYTES>>>(
        x, e0, e1, e2, e3, e4, Wd1, bd1, Wd2, bd2, Wc1, bc1, Wc2, bc2, out, N);
}